// round 1
// baseline (speedup 1.0000x reference)
#include <cuda_runtime.h>
#include <math.h>

#define B_SZ   8
#define L_SZ   2048
#define D_HALF 256
#define D_TYPE 32
#define HID    544          // 512 positional + 32 type
#define TI     32
#define TJ     128

// -------- scratch (no allocations allowed) --------
__device__ float g_pa[B_SZ * L_SZ];
__device__ float g_pb[B_SZ * L_SZ];
__device__ float g_ga[B_SZ * L_SZ];
__device__ float g_gb[B_SZ * L_SZ];
__device__ float g_div[D_HALF];

// -------- prep: per-(b,l) dot products + accurate div_term table --------
__global__ void prep_kernel(const int* __restrict__ etype,
                            const float* __restrict__ temb,
                            const float* __restrict__ wl,
                            const float* __restrict__ wg) {
    int idx = blockIdx.x * blockDim.x + threadIdx.x;
    if (idx < D_HALF) {
        // matches ref: exp(2k * (-ln(10000)/512)) computed in double, cast to f32
        g_div[idx] = (float)exp((double)(2 * idx) * (-log(10000.0) / 512.0));
    }
    if (idx < B_SZ * L_SZ) {
        int et = etype[idx];
        const float* te = temb + et * D_TYPE;
        float pa = 0.f, pb = 0.f, ga = 0.f, gb = 0.f;
#pragma unroll
        for (int k = 0; k < D_TYPE; ++k) {
            float v = te[k];
            pa += v * wl[k];
            pb += v * wl[D_TYPE + k];
            ga += v * wg[k];
            gb += v * wg[D_TYPE + k];
        }
        g_pa[idx] = pa; g_pb[idx] = pb;
        g_ga[idx] = ga; g_gb[idx] = gb;
    }
}

// -------- hidden vector: sin/cos(arc+phi) + type embedding --------
__global__ void __launch_bounds__(256) hidden_kernel(
    const int* __restrict__ etype,
    const float* __restrict__ etime,
    const float* __restrict__ Wt,
    const float* __restrict__ temb,
    float* __restrict__ out_hidden) {
    int bl = blockIdx.x;                 // b*L + l
    int k  = threadIdx.x;                // 0..255
    int l  = bl & (L_SZ - 1);
    float t   = etime[bl];
    float arc = (float)l * g_div[k];     // same fp32 product as reference
    float x   = arc + t * Wt[k];

    // Cody-Waite reduction x mod 2*pi  (|x| < 2100, n < 340)
    float n = rintf(x * 0.15915494309189535f);
    float r = fmaf(n, -6.28125f, x);                    // C1 exact in binary
    r = fmaf(n, -1.9353071795864769e-3f, r);            // C2
    float s, c;
    __sincosf(r, &s, &c);

    float* o = out_hidden + (size_t)bl * HID;
    o[k]           = s;
    o[D_HALF + k]  = c;
    if (k < D_TYPE)
        o[2 * D_HALF + k] = temb[etype[bl] * D_TYPE + k];
}

// -------- scores + t_diff --------
__device__ __forceinline__ float score1(float d, float paj, float gaj,
                                        float pbi, float gbi,
                                        float BLv, float BGv) {
    float xl = paj + pbi + BLv;
    // softplus(xl) = max(xl,0) + log1p(exp(-|xl|))
    float sp = fmaxf(xl, 0.f) + __logf(1.f + __expf(-fabsf(xl)));
    float rl = __fdividef(1.f, sp + 1e-6f);
    float u  = d * rl;
    float kk = 0.4f * __expf(-0.5f * u * u) + 0.3f * __expf(-u);
    float xg = 5.f * (gaj + gbi + BGv);
    float g  = __fdividef(1.f, 1.f + __expf(-xg));
    return g * kk;
}

__global__ void __launch_bounds__(256) pair_kernel(
    const float* __restrict__ etime,
    const float* __restrict__ p_bl,
    const float* __restrict__ p_bg,
    float* __restrict__ out_scores,
    float* __restrict__ out_tdiff) {

    int b  = blockIdx.z;
    int i0 = blockIdx.y * TI;
    int j0 = blockIdx.x * TJ;

    __shared__ float s_tj[TJ], s_paj[TJ], s_gaj[TJ];
    __shared__ float s_ti[TI], s_pbi[TI], s_gbi[TI];

    int tid = threadIdx.x;
    int off = b * L_SZ;
    if (tid < TJ) {
        int j = j0 + tid;
        s_tj[tid]  = etime[off + j];
        s_paj[tid] = g_pa[off + j];
        s_gaj[tid] = g_ga[off + j];
    } else if (tid < TJ + TI) {
        int il = tid - TJ;
        int i  = i0 + il;
        s_ti[il]  = etime[off + i];
        s_pbi[il] = g_pb[off + i];
        s_gbi[il] = g_gb[off + i];
    }
    __syncthreads();

    float BLv = __ldg(p_bl);
    float BGv = __ldg(p_bg);

    int jq = tid & 31;       // 32 quads of j (float4)
    int ir = tid >> 5;       // 8 row groups
    int jj = jq * 4;

    float4 tj = *(const float4*)&s_tj[jj];
    float4 pa = *(const float4*)&s_paj[jj];
    float4 ga = *(const float4*)&s_gaj[jj];

    bool zero_tile = (j0 >= i0 + TI);      // entire tile has j >= i -> scores 0
    bool full_tile = (j0 + TJ <= i0);      // entire tile has j <  i -> no mask

    size_t base = ((size_t)(off + i0)) * L_SZ + (size_t)(j0 + jj);

#pragma unroll
    for (int r = 0; r < 4; ++r) {
        int il = ir + r * 8;
        float ti = s_ti[il];
        float4 td;
        td.x = fabsf(tj.x - ti);
        td.y = fabsf(tj.y - ti);
        td.z = fabsf(tj.z - ti);
        td.w = fabsf(tj.w - ti);

        float4 sv;
        if (zero_tile) {
            sv = make_float4(0.f, 0.f, 0.f, 0.f);
        } else {
            float pbi = s_pbi[il], gbi = s_gbi[il];
            sv.x = score1(td.x, pa.x, ga.x, pbi, gbi, BLv, BGv);
            sv.y = score1(td.y, pa.y, ga.y, pbi, gbi, BLv, BGv);
            sv.z = score1(td.z, pa.z, ga.z, pbi, gbi, BLv, BGv);
            sv.w = score1(td.w, pa.w, ga.w, pbi, gbi, BLv, BGv);
            if (!full_tile) {
                int i = i0 + il;
                int j = j0 + jj;
                if (j     >= i) sv.x = 0.f;
                if (j + 1 >= i) sv.y = 0.f;
                if (j + 2 >= i) sv.z = 0.f;
                if (j + 3 >= i) sv.w = 0.f;
            }
        }
        size_t ofs = base + (size_t)il * L_SZ;
        __stcs((float4*)(out_scores + ofs), sv);
        __stcs((float4*)(out_tdiff  + ofs), td);
    }
}

extern "C" void kernel_launch(void* const* d_in, const int* in_sizes, int n_in,
                              void* d_out, int out_size) {
    const int*   etype = (const int*)  d_in[0];
    const float* etime = (const float*)d_in[1];
    // d_in[2] = arrival_times (unused by reference)
    const float* Wt    = (const float*)d_in[3];
    const float* temb  = (const float*)d_in[4];
    const float* wl    = (const float*)d_in[5];
    const float* p_bl  = (const float*)d_in[6];
    const float* wg    = (const float*)d_in[7];
    const float* p_bg  = (const float*)d_in[8];

    float* out = (float*)d_out;
    const size_t scoresN = (size_t)B_SZ * L_SZ * L_SZ;
    const size_t hidN    = (size_t)B_SZ * L_SZ * HID;
    float* out_scores = out;
    float* out_hidden = out + scoresN;
    float* out_tdiff  = out + scoresN + hidN;

    prep_kernel<<<(B_SZ * L_SZ + 255) / 256, 256>>>(etype, temb, wl, wg);
    hidden_kernel<<<B_SZ * L_SZ, 256>>>(etype, etime, Wt, temb, out_hidden);

    dim3 grid(L_SZ / TJ, L_SZ / TI, B_SZ);
    pair_kernel<<<grid, 256>>>(etime, p_bl, p_bg, out_scores, out_tdiff);
}